// round 1
// baseline (speedup 1.0000x reference)
#include <cuda_runtime.h>
#include <math.h>
#include <stdint.h>

// Problem dims
#define BQ     64
#define TQ     256
#define HQ     1024
#define LATQ   256
#define PQ     128
#define G4H    4096   // 4*H

// ---------------- device scratch (static, allocation-free) ----------------
__device__ float g_h0[BQ * HQ];                       // 256 KB
__device__ float g_hbuf[2][BQ * HQ];                  // ping-pong hidden state
__device__ float g_c[BQ * HQ];                        // cell state
__device__ float g_xg[(size_t)BQ * TQ * G4H];         // 256 MiB: precomputed input gates
__device__ float g_hseq[(size_t)BQ * TQ * HQ];        // 64 MiB: hidden sequence

// ---------------- helpers ----------------
__device__ __forceinline__ unsigned f2tf(float f) {
    unsigned u;
    asm("cvt.rna.tf32.f32 %0, %1;" : "=r"(u) : "f"(f));
    return u;
}
__device__ __forceinline__ float sigf(float x) { return 1.0f / (1.0f + expf(-x)); }

#define MMA_TF32(ACC, A0, A1, A2, A3, B0, B1)                                  \
    asm volatile(                                                              \
        "mma.sync.aligned.m16n8k8.row.col.f32.tf32.tf32.f32 "                  \
        "{%0,%1,%2,%3},{%4,%5,%6,%7},{%8,%9},{%0,%1,%2,%3};"                   \
        : "+f"((ACC)[0]), "+f"((ACC)[1]), "+f"((ACC)[2]), "+f"((ACC)[3])       \
        : "r"(A0), "r"(A1), "r"(A2), "r"(A3), "r"(B0), "r"(B1))

// ---------------- h0 = z @ fc_w^T + fc_b; seed h buffer and c ----------------
__global__ void k_h0(const float* __restrict__ z, const float* __restrict__ w,
                     const float* __restrict__ b) {
    int idx = blockIdx.x * blockDim.x + threadIdx.x;  // 0..65535
    int bb = idx >> 10, j = idx & 1023;
    const float4* zr = (const float4*)(z + bb * LATQ);
    const float4* wr = (const float4*)(w + (size_t)j * LATQ);
    float acc = 0.f;
#pragma unroll 8
    for (int k = 0; k < LATQ / 4; k++) {
        float4 a = zr[k], c = wr[k];
        acc += a.x * c.x + a.y * c.y + a.z * c.z + a.w * c.w;
    }
    float h = acc + b[j];
    g_h0[idx] = h;
    g_hbuf[0][idx] = h;
    g_c[idx] = 0.f;
}

// ---------------- reset h/c between layers ----------------
__global__ void k_reset() {
    int i = blockIdx.x * blockDim.x + threadIdx.x;
    g_hbuf[0][i] = g_h0[i];
    g_c[i] = 0.f;
}

// ---------------- generic tf32 GEMM: C[M,N] = A[M,K] @ W[N,K]^T + bias ----------------
// a_mode: 0 = Aparam, 1 = gather x_in(start_token/target_seq), 2 = g_hseq
// c_mode: 0 = g_xg, 1 = Cparam.  do_sig: apply sigmoid.
// CTA tile 64x64, 128 threads (4 warps, warp tile 32x32), K-tile 32.
__global__ void k_gemm(const float* __restrict__ Aparam,
                       const float* __restrict__ start_tok,
                       const float* __restrict__ target,
                       int a_mode,
                       const float* __restrict__ W, int K,
                       const float* __restrict__ bias1,
                       const float* __restrict__ bias2,
                       float* __restrict__ Cparam, int c_mode,
                       int ldc, int do_sig) {
    __shared__ float As[64][36];
    __shared__ float Ws[64][36];
    const int tid = threadIdx.x;        // 0..127
    const int lane = tid & 31, w = tid >> 5;
    const int n0 = blockIdx.x * 64, m0 = blockIdx.y * 64;
    const float* A = (a_mode == 2) ? g_hseq : Aparam;

    const int wm = (w >> 1) * 32, wn = (w & 1) * 32;
    float acc[2][4][4];
#pragma unroll
    for (int mt = 0; mt < 2; mt++)
#pragma unroll
        for (int j = 0; j < 4; j++)
#pragma unroll
            for (int c = 0; c < 4; c++) acc[mt][j][c] = 0.f;

    for (int k0 = 0; k0 < K; k0 += 32) {
        __syncthreads();
        // stage A tile (64x32), tf32-converted
#pragma unroll
        for (int i = 0; i < 4; i++) {
            int e = tid + i * 128;      // 0..511
            int row = e >> 3, q = e & 7;
            const float* src;
            if (a_mode == 1) {
                int m = m0 + row;
                int bb = m >> 8, t = m & 255;
                src = (t == 0) ? (start_tok + k0 + q * 4)
                               : (target + ((size_t)(bb * TQ + t - 1)) * PQ + k0 + q * 4);
            } else {
                src = A + (size_t)(m0 + row) * K + k0 + q * 4;
            }
            float4 v = *(const float4*)src;
            uint4 u = make_uint4(f2tf(v.x), f2tf(v.y), f2tf(v.z), f2tf(v.w));
            *(uint4*)&As[row][q * 4] = u;
        }
        // stage W tile (64x32)
#pragma unroll
        for (int i = 0; i < 4; i++) {
            int e = tid + i * 128;
            int row = e >> 3, q = e & 7;
            float4 v = *(const float4*)(W + (size_t)(n0 + row) * K + k0 + q * 4);
            uint4 u = make_uint4(f2tf(v.x), f2tf(v.y), f2tf(v.z), f2tf(v.w));
            *(uint4*)&Ws[row][q * 4] = u;
        }
        __syncthreads();
#pragma unroll
        for (int kk = 0; kk < 32; kk += 8) {
            unsigned a[2][4], bf[4][2];
#pragma unroll
            for (int mt = 0; mt < 2; mt++) {
                int r = wm + 16 * mt + (lane >> 2);
                int c = kk + (lane & 3);
                a[mt][0] = __float_as_uint(As[r][c]);
                a[mt][1] = __float_as_uint(As[r + 8][c]);
                a[mt][2] = __float_as_uint(As[r][c + 4]);
                a[mt][3] = __float_as_uint(As[r + 8][c + 4]);
            }
#pragma unroll
            for (int j = 0; j < 4; j++) {
                int r = wn + 8 * j + (lane >> 2);
                int c = kk + (lane & 3);
                bf[j][0] = __float_as_uint(Ws[r][c]);
                bf[j][1] = __float_as_uint(Ws[r][c + 4]);
            }
#pragma unroll
            for (int mt = 0; mt < 2; mt++)
#pragma unroll
                for (int j = 0; j < 4; j++)
                    MMA_TF32(acc[mt][j], a[mt][0], a[mt][1], a[mt][2], a[mt][3],
                             bf[j][0], bf[j][1]);
        }
    }

    float* Cout = (c_mode == 1) ? Cparam : g_xg;
#pragma unroll
    for (int mt = 0; mt < 2; mt++)
#pragma unroll
        for (int j = 0; j < 4; j++)
#pragma unroll
            for (int ci = 0; ci < 4; ci++) {
                int row = m0 + wm + 16 * mt + (lane >> 2) + ((ci >> 1) << 3);
                int col = n0 + wn + 8 * j + 2 * (lane & 3) + (ci & 1);
                float v = acc[mt][j][ci] + bias1[col];
                if (bias2) v += bias2[col];
                if (do_sig) v = sigf(v);
                Cout[(size_t)row * ldc + col] = v;
            }
}

// ---------------- recurrent step: gates = xg_t + h @ Whh^T, fused LSTM cell ----------------
// grid 128 CTAs (each owns 8 h-columns => 32 gate rows: 4 gates x 8 cols),
// 128 threads = 4 warps, warp tile 16x32, K = 1024 in tiles of 32.
__global__ void k_step(const float* __restrict__ Whh, int t) {
    __shared__ float As[64][36];   // h tile: full batch x 32 k
    __shared__ float Ws[32][36];   // gathered Whh rows
    const int tid = threadIdx.x;   // 0..127
    const int lane = tid & 31, w = tid >> 5;
    const int c0 = blockIdx.x * 8;
    const float* __restrict__ h_in = g_hbuf[t & 1];
    float* __restrict__ h_out = g_hbuf[(t + 1) & 1];

    float acc[4][4];
#pragma unroll
    for (int j = 0; j < 4; j++)
#pragma unroll
        for (int c = 0; c < 4; c++) acc[j][c] = 0.f;

    for (int k0 = 0; k0 < HQ; k0 += 32) {
        __syncthreads();
        // stage h tile: 64 rows x 32 cols = 512 float4, 4 per thread
#pragma unroll
        for (int i = 0; i < 4; i++) {
            int e = tid + i * 128;
            int row = e >> 3, q = e & 7;
            float4 v = *(const float4*)(h_in + row * HQ + k0 + q * 4);
            uint4 u = make_uint4(f2tf(v.x), f2tf(v.y), f2tf(v.z), f2tf(v.w));
            *(uint4*)&As[row][q * 4] = u;
        }
        // stage Whh rows: local row j -> global row (j>>3)*H + c0 + (j&7)
#pragma unroll
        for (int i = 0; i < 2; i++) {
            int e = tid + i * 128;  // 0..255
            int row = e >> 3, q = e & 7;
            int grow = (row >> 3) * HQ + c0 + (row & 7);
            float4 v = *(const float4*)(Whh + (size_t)grow * HQ + k0 + q * 4);
            uint4 u = make_uint4(f2tf(v.x), f2tf(v.y), f2tf(v.z), f2tf(v.w));
            *(uint4*)&Ws[row][q * 4] = u;
        }
        __syncthreads();
#pragma unroll
        for (int kk = 0; kk < 32; kk += 8) {
            int r = 16 * w + (lane >> 2);
            int c = kk + (lane & 3);
            unsigned a0 = __float_as_uint(As[r][c]);
            unsigned a1 = __float_as_uint(As[r + 8][c]);
            unsigned a2 = __float_as_uint(As[r][c + 4]);
            unsigned a3 = __float_as_uint(As[r + 8][c + 4]);
#pragma unroll
            for (int jt = 0; jt < 4; jt++) {
                int br = 8 * jt + (lane >> 2);
                unsigned b0 = __float_as_uint(Ws[br][c]);
                unsigned b1 = __float_as_uint(Ws[br][c + 4]);
                MMA_TF32(acc[jt], a0, a1, a2, a3, b0, b1);
            }
        }
    }

    // fused LSTM cell: each lane holds i,f,g,o for its 4 (b, col) cells locally
#pragma unroll
    for (int ci = 0; ci < 4; ci++) {
        int b = 16 * w + (lane >> 2) + ((ci >> 1) << 3);
        int jc = 2 * (lane & 3) + (ci & 1);
        int col = c0 + jc;
        size_t xr = ((size_t)b * TQ + t) * G4H;
        float ig = acc[0][ci] + g_xg[xr + col];
        float fg = acc[1][ci] + g_xg[xr + HQ + col];
        float gg = acc[2][ci] + g_xg[xr + 2 * HQ + col];
        float og = acc[3][ci] + g_xg[xr + 3 * HQ + col];
        float iv = sigf(ig), fv = sigf(fg), gv = tanhf(gg), ov = sigf(og);
        int cidx = b * HQ + col;
        float cn = fv * g_c[cidx] + iv * gv;
        g_c[cidx] = cn;
        float hn = ov * tanhf(cn);
        h_out[cidx] = hn;
        g_hseq[((size_t)b * TQ + t) * HQ + col] = hn;
    }
}

// ---------------- launch ----------------
extern "C" void kernel_launch(void* const* d_in, const int* in_sizes, int n_in,
                              void* d_out, int out_size) {
    (void)in_sizes; (void)n_in; (void)out_size;
    const float* z      = (const float*)d_in[0];
    const float* target = (const float*)d_in[1];
    const float* fcw    = (const float*)d_in[2];
    const float* fcb    = (const float*)d_in[3];
    const float* start  = (const float*)d_in[4];
    const float* Wih0   = (const float*)d_in[5];
    const float* Whh0   = (const float*)d_in[6];
    const float* bih0   = (const float*)d_in[7];
    const float* bhh0   = (const float*)d_in[8];
    const float* Wih1   = (const float*)d_in[9];
    const float* Whh1   = (const float*)d_in[10];
    const float* bih1   = (const float*)d_in[11];
    const float* bhh1   = (const float*)d_in[12];
    const float* outw   = (const float*)d_in[13];
    const float* outb   = (const float*)d_in[14];
    float* out = (float*)d_out;

    // h0 = fc_init(z); seed h buffer 0 and c = 0
    k_h0<<<256, 256>>>(z, fcw, fcb);

    // xg0 = x_in @ Wih0^T + bih0 + bhh0   (x_in gathered: start token / shifted target)
    k_gemm<<<dim3(G4H / 64, (BQ * TQ) / 64), 128>>>(
        nullptr, start, target, /*a_mode=*/1, Wih0, PQ, bih0, bhh0,
        nullptr, /*c_mode=*/0, G4H, 0);

    // layer 0 recurrence
    for (int t = 0; t < TQ; t++) k_step<<<128, 128>>>(Whh0, t);

    // reset h/c for layer 1
    k_reset<<<256, 256>>>();

    // xg1 = h1 @ Wih1^T + bih1 + bhh1  (reads g_hseq, overwrites g_xg)
    k_gemm<<<dim3(G4H / 64, (BQ * TQ) / 64), 128>>>(
        nullptr, nullptr, nullptr, /*a_mode=*/2, Wih1, HQ, bih1, bhh1,
        nullptr, /*c_mode=*/0, G4H, 0);

    // layer 1 recurrence (overwrites g_hseq with h2)
    for (int t = 0; t < TQ; t++) k_step<<<128, 128>>>(Whh1, t);

    // out = sigmoid(h2 @ out_w^T + out_b)
    k_gemm<<<dim3(PQ / 64, (BQ * TQ) / 64), 128>>>(
        nullptr, nullptr, nullptr, /*a_mode=*/2, outw, HQ, outb, nullptr,
        out, /*c_mode=*/1, PQ, /*do_sig=*/1);
}

// round 2
// speedup vs baseline: 3.2727x; 3.2727x over previous
#include <cuda_runtime.h>
#include <cuda_bf16.h>
#include <math.h>
#include <stdint.h>

// Problem dims
#define BQ     64
#define TQ     256
#define HQ     1024
#define LATQ   256
#define PQ     128
#define G4H    4096   // 4*H
#define NCTA   128

// ---------------- device scratch (static, allocation-free) ----------------
__device__ float g_h0[BQ * HQ];
__device__ __align__(256) __nv_bfloat16 g_hb[2][BQ * HQ];   // ping-pong hidden (bf16)
__device__ float g_xg[(size_t)BQ * TQ * G4H];               // 256 MiB input gates
__device__ float g_hseq[(size_t)BQ * TQ * HQ];              // 64 MiB hidden sequence (fp32)
__device__ unsigned g_bar;                                  // grid barrier counter

// ---------------- helpers ----------------
__device__ __forceinline__ unsigned f2tf(float f) {
    unsigned u;
    asm("cvt.rna.tf32.f32 %0, %1;" : "=r"(u) : "f"(f));
    return u;
}
__device__ __forceinline__ float sigf(float x) { return 1.0f / (1.0f + expf(-x)); }

#define MMA_TF32(ACC, A0, A1, A2, A3, B0, B1)                                  \
    asm volatile(                                                              \
        "mma.sync.aligned.m16n8k8.row.col.f32.tf32.tf32.f32 "                  \
        "{%0,%1,%2,%3},{%4,%5,%6,%7},{%8,%9},{%0,%1,%2,%3};"                   \
        : "+f"((ACC)[0]), "+f"((ACC)[1]), "+f"((ACC)[2]), "+f"((ACC)[3])       \
        : "r"(A0), "r"(A1), "r"(A2), "r"(A3), "r"(B0), "r"(B1))

#define MMA_BF16(ACC, A0, A1, A2, A3, B0, B1)                                  \
    asm volatile(                                                              \
        "mma.sync.aligned.m16n8k16.row.col.f32.bf16.bf16.f32 "                 \
        "{%0,%1,%2,%3},{%4,%5,%6,%7},{%8,%9},{%0,%1,%2,%3};"                   \
        : "+f"((ACC)[0]), "+f"((ACC)[1]), "+f"((ACC)[2]), "+f"((ACC)[3])       \
        : "r"(A0), "r"(A1), "r"(A2), "r"(A3), "r"(B0), "r"(B1))

__device__ __forceinline__ void ldsm4(unsigned& r0, unsigned& r1, unsigned& r2,
                                      unsigned& r3, unsigned addr) {
    asm volatile("ldmatrix.sync.aligned.m8n8.x4.shared.b16 {%0,%1,%2,%3}, [%4];"
                 : "=r"(r0), "=r"(r1), "=r"(r2), "=r"(r3) : "r"(addr));
}
__device__ __forceinline__ void cp16(unsigned dst, const void* src) {
    asm volatile("cp.async.ca.shared.global [%0], [%1], 16;" :: "r"(dst), "l"(src));
}
#define CP_COMMIT() asm volatile("cp.async.commit_group;")
#define CP_WAIT(n)  asm volatile("cp.async.wait_group %0;" :: "n"(n))

// ---------------- h0 = z @ fc_w^T + fc_b; seed bf16 h buffer; reset barrier ----------------
__global__ void k_h0(const float* __restrict__ z, const float* __restrict__ w,
                     const float* __restrict__ b) {
    int idx = blockIdx.x * blockDim.x + threadIdx.x;  // 0..65535
    int bb = idx >> 10, j = idx & 1023;
    const float4* zr = (const float4*)(z + bb * LATQ);
    const float4* wr = (const float4*)(w + (size_t)j * LATQ);
    float acc = 0.f;
#pragma unroll 8
    for (int k = 0; k < LATQ / 4; k++) {
        float4 a = zr[k], c = wr[k];
        acc += a.x * c.x + a.y * c.y + a.z * c.z + a.w * c.w;
    }
    float h = acc + b[j];
    g_h0[idx] = h;
    g_hb[0][idx] = __float2bfloat16_rn(h);
    if (idx == 0) g_bar = 0;
}

// ---------------- reset h between layers ----------------
__global__ void k_reset() {
    int i = blockIdx.x * blockDim.x + threadIdx.x;
    g_hb[0][i] = __float2bfloat16_rn(g_h0[i]);
}

// ---------------- generic tf32 GEMM: C[M,N] = A[M,K] @ W[N,K]^T + bias ----------------
__global__ void k_gemm(const float* __restrict__ Aparam,
                       const float* __restrict__ start_tok,
                       const float* __restrict__ target,
                       int a_mode,
                       const float* __restrict__ W, int K,
                       const float* __restrict__ bias1,
                       const float* __restrict__ bias2,
                       float* __restrict__ Cparam, int c_mode,
                       int ldc, int do_sig) {
    __shared__ float As[64][36];
    __shared__ float Ws[64][36];
    const int tid = threadIdx.x;        // 0..127
    const int lane = tid & 31, w = tid >> 5;
    const int n0 = blockIdx.x * 64, m0 = blockIdx.y * 64;
    const float* A = (a_mode == 2) ? g_hseq : Aparam;

    const int wm = (w >> 1) * 32, wn = (w & 1) * 32;
    float acc[2][4][4];
#pragma unroll
    for (int mt = 0; mt < 2; mt++)
#pragma unroll
        for (int j = 0; j < 4; j++)
#pragma unroll
            for (int c = 0; c < 4; c++) acc[mt][j][c] = 0.f;

    for (int k0 = 0; k0 < K; k0 += 32) {
        __syncthreads();
#pragma unroll
        for (int i = 0; i < 4; i++) {
            int e = tid + i * 128;
            int row = e >> 3, q = e & 7;
            const float* src;
            if (a_mode == 1) {
                int m = m0 + row;
                int bb = m >> 8, t = m & 255;
                src = (t == 0) ? (start_tok + k0 + q * 4)
                               : (target + ((size_t)(bb * TQ + t - 1)) * PQ + k0 + q * 4);
            } else {
                src = A + (size_t)(m0 + row) * K + k0 + q * 4;
            }
            float4 v = *(const float4*)src;
            uint4 u = make_uint4(f2tf(v.x), f2tf(v.y), f2tf(v.z), f2tf(v.w));
            *(uint4*)&As[row][q * 4] = u;
        }
#pragma unroll
        for (int i = 0; i < 4; i++) {
            int e = tid + i * 128;
            int row = e >> 3, q = e & 7;
            float4 v = *(const float4*)(W + (size_t)(n0 + row) * K + k0 + q * 4);
            uint4 u = make_uint4(f2tf(v.x), f2tf(v.y), f2tf(v.z), f2tf(v.w));
            *(uint4*)&Ws[row][q * 4] = u;
        }
        __syncthreads();
#pragma unroll
        for (int kk = 0; kk < 32; kk += 8) {
            unsigned a[2][4], bf[4][2];
#pragma unroll
            for (int mt = 0; mt < 2; mt++) {
                int r = wm + 16 * mt + (lane >> 2);
                int c = kk + (lane & 3);
                a[mt][0] = __float_as_uint(As[r][c]);
                a[mt][1] = __float_as_uint(As[r + 8][c]);
                a[mt][2] = __float_as_uint(As[r][c + 4]);
                a[mt][3] = __float_as_uint(As[r + 8][c + 4]);
            }
#pragma unroll
            for (int j = 0; j < 4; j++) {
                int r = wn + 8 * j + (lane >> 2);
                int c = kk + (lane & 3);
                bf[j][0] = __float_as_uint(Ws[r][c]);
                bf[j][1] = __float_as_uint(Ws[r][c + 4]);
            }
#pragma unroll
            for (int mt = 0; mt < 2; mt++)
#pragma unroll
                for (int j = 0; j < 4; j++)
                    MMA_TF32(acc[mt][j], a[mt][0], a[mt][1], a[mt][2], a[mt][3],
                             bf[j][0], bf[j][1]);
        }
    }

    float* Cout = (c_mode == 1) ? Cparam : g_xg;
#pragma unroll
    for (int mt = 0; mt < 2; mt++)
#pragma unroll
        for (int j = 0; j < 4; j++)
#pragma unroll
            for (int ci = 0; ci < 4; ci++) {
                int row = m0 + wm + 16 * mt + (lane >> 2) + ((ci >> 1) << 3);
                int col = n0 + wn + 8 * j + 2 * (lane & 3) + (ci & 1);
                float v = acc[mt][j][ci] + bias1[col];
                if (bias2) v += bias2[col];
                if (do_sig) v = sigf(v);
                Cout[(size_t)row * ldc + col] = v;
            }
}

// ---------------- persistent recurrent kernel (one launch per layer) ----------------
// 128 CTAs x 256 threads; CTA owns 8 h-columns. Whh slice resident in smem (bf16).
// 8 warps: warps 0-3 accumulate k in [0,512), warps 4-7 k in [512,1024); smem reduce.
// c lives in registers for all 256 steps. Grid barrier per step (all CTAs co-resident).
#define WS_STRIDE 1032
#define WS_BYTES  (32 * WS_STRIDE * 2)       // 66048
#define HS_STRIDE 72
#define HS_BYTES  (2 * 2 * 64 * HS_STRIDE * 2)  // 36864
#define REC_SMEM  (WS_BYTES + HS_BYTES)

__global__ void __launch_bounds__(256, 1) k_rec(const float* __restrict__ Whh,
                                                unsigned bar_base) {
    extern __shared__ char sm[];
    __nv_bfloat16* Ws = (__nv_bfloat16*)sm;
    __nv_bfloat16* Hs = (__nv_bfloat16*)(sm + WS_BYTES);
    float* red = (float*)(sm + WS_BYTES);   // reused after k-loop
    const int tid = threadIdx.x;
    const int lane = tid & 31;
    const int w = tid >> 5;       // 0..7
    const int ww = w & 3;         // warp within half
    const int wh = tid >> 7;      // K-half id
    const int tid128 = tid & 127;
    const int c0 = blockIdx.x * 8;

    // Load this CTA's Whh slice (32 gate-rows x 1024) -> smem bf16, once.
#pragma unroll 4
    for (int i = 0; i < 32; i++) {
        int e = tid + i * 256;            // 0..8191 float4 units
        int row = e >> 8, q = e & 255;
        int grow = (row >> 3) * HQ + c0 + (row & 7);
        float4 v = *(const float4*)(Whh + (size_t)grow * HQ + q * 4);
        __nv_bfloat16* d = Ws + row * WS_STRIDE + q * 4;
        d[0] = __float2bfloat16_rn(v.x); d[1] = __float2bfloat16_rn(v.y);
        d[2] = __float2bfloat16_rn(v.z); d[3] = __float2bfloat16_rn(v.w);
    }
    __syncthreads();

    float c_reg[4] = {0.f, 0.f, 0.f, 0.f};

    for (int t = 0; t < TQ; t++) {
        const __nv_bfloat16* __restrict__ hin = g_hb[t & 1];
        __nv_bfloat16* __restrict__ hout = g_hb[(t + 1) & 1];

        // Prefetch xg for this step (lower warps only; independent of h)
        float xgv[4][4];
        if (w < 4) {
#pragma unroll
            for (int ci = 0; ci < 4; ci++) {
                int b = 16 * ww + (lane >> 2) + 8 * (ci >> 1);
                int col = c0 + 2 * (lane & 3) + (ci & 1);
                size_t base = ((size_t)b * TQ + t) * G4H + col;
#pragma unroll
                for (int g = 0; g < 4; g++) xgv[g][ci] = g_xg[base + g * HQ];
            }
        }

        float acc[4][4];
#pragma unroll
        for (int j = 0; j < 4; j++)
#pragma unroll
            for (int ci = 0; ci < 4; ci++) acc[j][ci] = 0.f;

        // --- pipelined K loop: 8 tiles of 64 per half ---
        int buf = 0;
        {   // stage tile 0
            int row = tid128 >> 3, ch = tid128 & 7;
#pragma unroll
            for (int i = 0; i < 4; i++) {
                int rr = row + i * 16;
                const void* src = hin + (size_t)rr * HQ + wh * 512 + ch * 8;
                unsigned dst = (unsigned)__cvta_generic_to_shared(
                    Hs + ((0 * 2 + wh) * 64 + rr) * HS_STRIDE + ch * 8);
                cp16(dst, src);
            }
            CP_COMMIT();
        }
        for (int it = 0; it < 8; it++) {
            if (it < 7) {
                int row = tid128 >> 3, ch = tid128 & 7;
                int kb = wh * 512 + (it + 1) * 64;
#pragma unroll
                for (int i = 0; i < 4; i++) {
                    int rr = row + i * 16;
                    const void* src = hin + (size_t)rr * HQ + kb + ch * 8;
                    unsigned dst = (unsigned)__cvta_generic_to_shared(
                        Hs + (((buf ^ 1) * 2 + wh) * 64 + rr) * HS_STRIDE + ch * 8);
                    cp16(dst, src);
                }
                CP_COMMIT();
                CP_WAIT(1);
            } else {
                CP_WAIT(0);
            }
            asm volatile("bar.sync %0, 128;" :: "r"(1 + wh));  // tile ready (per half)
#pragma unroll
            for (int kk = 0; kk < 64; kk += 16) {
                unsigned a0, a1, a2, a3;
                {
                    int tl = lane >> 3, r = lane & 7;
                    int row = 16 * ww + (tl & 1) * 8 + r;
                    int col = kk + (tl >> 1) * 8;
                    unsigned ad = (unsigned)__cvta_generic_to_shared(
                        Hs + ((buf * 2 + wh) * 64 + row) * HS_STRIDE + col);
                    ldsm4(a0, a1, a2, a3, ad);
                }
                unsigned b0[4], b1[4];
                {
                    int kg = wh * 512 + it * 64 + kk;
                    unsigned ad0 = (unsigned)__cvta_generic_to_shared(
                        Ws + lane * WS_STRIDE + kg);
                    ldsm4(b0[0], b0[1], b0[2], b0[3], ad0);
                    unsigned ad1 = (unsigned)__cvta_generic_to_shared(
                        Ws + lane * WS_STRIDE + kg + 8);
                    ldsm4(b1[0], b1[1], b1[2], b1[3], ad1);
                }
#pragma unroll
                for (int j = 0; j < 4; j++)
                    MMA_BF16(acc[j], a0, a1, a2, a3, b0[j], b1[j]);
            }
            asm volatile("bar.sync %0, 128;" :: "r"(1 + wh));  // done reading buf
            buf ^= 1;
        }

        // --- reduce the two K-halves ---
        __syncthreads();
        if (w >= 4) {
            float* p = red + ((w - 4) * 32 + lane) * 16;
#pragma unroll
            for (int j = 0; j < 4; j++)
#pragma unroll
                for (int ci = 0; ci < 4; ci++) p[j * 4 + ci] = acc[j][ci];
        }
        __syncthreads();
        if (w < 4) {
            const float* p = red + (w * 32 + lane) * 16;
#pragma unroll
            for (int j = 0; j < 4; j++)
#pragma unroll
                for (int ci = 0; ci < 4; ci++) acc[j][ci] += p[j * 4 + ci];

            // --- fused LSTM cell, c in registers ---
#pragma unroll
            for (int ci = 0; ci < 4; ci++) {
                int b = 16 * ww + (lane >> 2) + 8 * (ci >> 1);
                int col = c0 + 2 * (lane & 3) + (ci & 1);
                float ig = acc[0][ci] + xgv[0][ci];
                float fg = acc[1][ci] + xgv[1][ci];
                float gg = acc[2][ci] + xgv[2][ci];
                float og = acc[3][ci] + xgv[3][ci];
                float cn = sigf(fg) * c_reg[ci] + sigf(ig) * tanhf(gg);
                c_reg[ci] = cn;
                float hn = sigf(og) * tanhf(cn);
                hout[b * HQ + col] = __float2bfloat16_rn(hn);
                g_hseq[((size_t)b * TQ + t) * HQ + col] = hn;
            }
        }

        // --- grid barrier ---
        __threadfence();
        __syncthreads();
        if (tid == 0) {
            atomicAdd(&g_bar, 1u);
            unsigned target = bar_base + (unsigned)(t + 1) * NCTA;
            while (atomicAdd(&g_bar, 0u) < target) {}
            __threadfence();
        }
        __syncthreads();
    }
}

// ---------------- launch ----------------
extern "C" void kernel_launch(void* const* d_in, const int* in_sizes, int n_in,
                              void* d_out, int out_size) {
    (void)in_sizes; (void)n_in; (void)out_size;
    const float* z      = (const float*)d_in[0];
    const float* target = (const float*)d_in[1];
    const float* fcw    = (const float*)d_in[2];
    const float* fcb    = (const float*)d_in[3];
    const float* start  = (const float*)d_in[4];
    const float* Wih0   = (const float*)d_in[5];
    const float* Whh0   = (const float*)d_in[6];
    const float* bih0   = (const float*)d_in[7];
    const float* bhh0   = (const float*)d_in[8];
    const float* Wih1   = (const float*)d_in[9];
    const float* Whh1   = (const float*)d_in[10];
    const float* bih1   = (const float*)d_in[11];
    const float* bhh1   = (const float*)d_in[12];
    const float* outw   = (const float*)d_in[13];
    const float* outb   = (const float*)d_in[14];
    float* out = (float*)d_out;

    cudaFuncSetAttribute(k_rec, cudaFuncAttributeMaxDynamicSharedMemorySize, REC_SMEM);

    // h0 = fc_init(z); seed bf16 h buffer; reset grid barrier
    k_h0<<<256, 256>>>(z, fcw, fcb);

    // xg0 = x_in @ Wih0^T + bih0 + bhh0
    k_gemm<<<dim3(G4H / 64, (BQ * TQ) / 64), 128>>>(
        nullptr, start, target, 1, Wih0, PQ, bih0, bhh0, nullptr, 0, G4H, 0);

    // layer 0 recurrence (persistent)
    k_rec<<<NCTA, 256, REC_SMEM>>>(Whh0, 0u);

    // reset h for layer 1
    k_reset<<<256, 256>>>();

    // xg1 = h1 @ Wih1^T + bih1 + bhh1
    k_gemm<<<dim3(G4H / 64, (BQ * TQ) / 64), 128>>>(
        nullptr, nullptr, nullptr, 2, Wih1, HQ, bih1, bhh1, nullptr, 0, G4H, 0);

    // layer 1 recurrence (persistent)
    k_rec<<<NCTA, 256, REC_SMEM>>>(Whh1, (unsigned)(NCTA * TQ));

    // out = sigmoid(h2 @ out_w^T + out_b)
    k_gemm<<<dim3(PQ / 64, (BQ * TQ) / 64), 128>>>(
        nullptr, nullptr, nullptr, 2, outw, HQ, outb, nullptr, out, 1, PQ, 1);
}